// round 1
// baseline (speedup 1.0000x reference)
#include <cuda_runtime.h>

#define B_   512
#define T_   4096
#define TILE 256

typedef unsigned long long u64;

// ---- packed f32x2 helpers (ptxas won't auto-fuse; PTX-only path on sm_103a) ----
__device__ __forceinline__ u64 pk(float lo, float hi) {
    u64 r; asm("mov.b64 %0,{%1,%2};" : "=l"(r) : "f"(lo), "f"(hi)); return r;
}
__device__ __forceinline__ void upk(u64 v, float& lo, float& hi) {
    asm("mov.b64 {%0,%1},%2;" : "=f"(lo), "=f"(hi) : "l"(v));
}
__device__ __forceinline__ u64 ffma2(u64 a, u64 b, u64 c) {
    u64 d; asm("fma.rn.f32x2 %0,%1,%2,%3;" : "=l"(d) : "l"(a), "l"(b), "l"(c)); return d;
}
__device__ __forceinline__ u64 fmul2(u64 a, u64 b) {
    u64 d; asm("mul.rn.f32x2 %0,%1,%2;" : "=l"(d) : "l"(a), "l"(b)); return d;
}
__device__ __forceinline__ u64 fadd2(u64 a, u64 b) {
    u64 d; asm("add.rn.f32x2 %0,%1,%2;" : "=l"(d) : "l"(a), "l"(b)); return d;
}

// x smem tile: rows of 8 pairs (xL[c], xR[c]), padded to 9 u64 (72B) per row
// so STS.64/LDS.64 across consecutive rows are bank-conflict-free.
#define XROW 9

__global__ __launch_bounds__(256)
void bimanual_kernel(const float* __restrict__ x,
                     const float* __restrict__ conv_w, const float* __restrict__ conv_b,
                     const float* __restrict__ w1, const float* __restrict__ b1,
                     const float* __restrict__ w2, const float* __restrict__ b2,
                     const float* __restrict__ ln_g, const float* __restrict__ ln_b,
                     float* __restrict__ out)
{
    __shared__ __align__(16) u64   xs[(TILE + 2) * XROW];   // pair-interleaved x tile
    __shared__ __align__(16) u64   cwp[16 * 24];            // conv weights, (w,w) pairs, [oc][k][ic]
    __shared__ __align__(16) float w1s[512];                // w1 raw (32,16): row f gives hidden-pair weights
    __shared__ u64   cbp[16];                               // conv bias pairs
    __shared__ u64   b1p[8];                                // b1 as hidden-output pairs
    __shared__ __align__(8) float w2s[32];                  // w2 raw (16,2): row h = (w2[h][0], w2[h][1])
    __shared__ u64   b2p_s[1];
    __shared__ u64   gp[8], bp[8];                          // ln gamma/beta packed (c, c+8)

    const int tid   = threadIdx.x;
    const int b     = blockIdx.y;
    const int tbase = blockIdx.x * TILE;

    // ---- stage x tile (TILE + 2 halo rows; t<0 rows are the conv zero-padding) ----
    for (int tt = tid; tt < TILE + 2; tt += 256) {
        const int t = tbase - 2 + tt;
        u64* row = &xs[tt * XROW];
        if (t >= 0) {
            const float4* p = (const float4*)(x + ((size_t)b * T_ + t) * 16);
            float4 a = p[0], bq = p[1], c = p[2], d = p[3];
            row[0] = pk(a.x,  c.x); row[1] = pk(a.y,  c.y);
            row[2] = pk(a.z,  c.z); row[3] = pk(a.w,  c.w);
            row[4] = pk(bq.x, d.x); row[5] = pk(bq.y, d.y);
            row[6] = pk(bq.z, d.z); row[7] = pk(bq.w, d.w);
        } else {
            #pragma unroll
            for (int j = 0; j < 8; ++j) row[j] = 0ull;
        }
    }

    // ---- stage weights (broadcast-read later; pre-packed (w,w) for f32x2) ----
    for (int j = tid; j < 384; j += 256) {
        const int oc = j / 24, r = j % 24, ic = r / 3, k = r % 3;  // conv_w is (oc, ic, k)
        const float w = conv_w[j];
        cwp[oc * 24 + k * 8 + ic] = pk(w, w);
    }
    for (int j = tid; j < 512; j += 256) w1s[j] = w1[j];
    if (tid < 16) cbp[tid]   = pk(conv_b[tid], conv_b[tid]);
    if (tid < 8)  b1p[tid]   = pk(b1[2 * tid], b1[2 * tid + 1]);
    if (tid < 32) w2s[tid]   = w2[tid];
    if (tid == 0) b2p_s[0]   = pk(b2[0], b2[1]);
    if (tid < 8)  gp[tid]    = pk(ln_g[tid], ln_g[tid + 8]);
    if (tid < 8)  bp[tid]    = pk(ln_b[tid], ln_b[tid + 8]);
    __syncthreads();

    // ---- per-thread element: global t = tbase + tid ----
    const int tl = tid;

    // 3-tap window of packed (L,R) channel pairs: xp[k][ic] ↔ x[t-2+k][ic | ic+8]
    u64 xp[3][8];
    #pragma unroll
    for (int k = 0; k < 3; ++k) {
        const u64* row = &xs[(tl + k) * XROW];
        #pragma unroll
        for (int ic = 0; ic < 8; ++ic) xp[k][ic] = row[ic];
    }

    // ---- causal conv (both streams per FFMA2) + ReLU → Hcat[32] ----
    float hcat[32];
    #pragma unroll
    for (int oc = 0; oc < 16; ++oc) {
        u64 acc = cbp[oc];
        #pragma unroll
        for (int k = 0; k < 3; ++k) {
            const ulonglong2* wp = (const ulonglong2*)&cwp[oc * 24 + k * 8];
            #pragma unroll
            for (int q = 0; q < 4; ++q) {
                const ulonglong2 wv = wp[q];          // LDS.128 = 2 packed weight pairs
                acc = ffma2(xp[k][2 * q],     wv.x, acc);
                acc = ffma2(xp[k][2 * q + 1], wv.y, acc);
            }
        }
        float hl, hr; upk(acc, hl, hr);
        hcat[oc]      = fmaxf(hl, 0.f);
        hcat[16 + oc] = fmaxf(hr, 0.f);
    }

    // ---- hidden = relu(Hcat @ w1 + b1), packed as 8 output pairs ----
    u64 hacc[8];
    #pragma unroll
    for (int j = 0; j < 8; ++j) hacc[j] = b1p[j];
    #pragma unroll
    for (int f = 0; f < 32; ++f) {
        const u64 vb = pk(hcat[f], hcat[f]);
        const ulonglong2* wf = (const ulonglong2*)&w1s[f * 16];
        #pragma unroll
        for (int q = 0; q < 4; ++q) {
            const ulonglong2 wv = wf[q];              // weights for hidden outputs 4q..4q+3
            hacc[2 * q]     = ffma2(vb, wv.x, hacc[2 * q]);
            hacc[2 * q + 1] = ffma2(vb, wv.y, hacc[2 * q + 1]);
        }
    }

    // ---- logits (both in one f32x2 lane pair) + softmax over 2 ----
    u64 lacc = b2p_s[0];
    const u64* w2p = (const u64*)w2s;                 // w2p[h] = (w2[h][0], w2[h][1])
    #pragma unroll
    for (int j = 0; j < 8; ++j) {
        float h0, h1; upk(hacc[j], h0, h1);
        h0 = fmaxf(h0, 0.f); h1 = fmaxf(h1, 0.f);
        lacc = ffma2(pk(h0, h0), w2p[2 * j],     lacc);
        lacc = ffma2(pk(h1, h1), w2p[2 * j + 1], lacc);
    }
    float l0, l1; upk(lacc, l0, l1);
    const float e  = __expf(l1 - l0);
    const float a0 = 1.f / (1.f + e);
    const float a1 = e * a0;

    // ---- gated residual + LayerNorm(16), all in packed (L,R) lanes ----
    const u64 sp = pk(1.f + a0, 1.f + a1);            // y = x * (1 + alpha_side)
    u64 yp[8];
    u64 sum = pk(0.f, 0.f);
    #pragma unroll
    for (int c = 0; c < 8; ++c) { yp[c] = fmul2(xp[2][c], sp); sum = fadd2(sum, yp[c]); }
    float sL, sR; upk(sum, sL, sR);
    const float mu   = (sL + sR) * 0.0625f;
    const u64   nmup = pk(-mu, -mu);
    u64 var2 = pk(0.f, 0.f);
    u64 dp[8];
    #pragma unroll
    for (int c = 0; c < 8; ++c) { dp[c] = fadd2(yp[c], nmup); var2 = ffma2(dp[c], dp[c], var2); }
    float vL, vR; upk(var2, vL, vR);
    const float rs  = rsqrtf((vL + vR) * 0.0625f + 1e-5f);
    const u64   rsp = pk(rs, rs);

    float o[16];
    #pragma unroll
    for (int c = 0; c < 8; ++c) {
        const u64 op = ffma2(fmul2(dp[c], rsp), gp[c], bp[c]);
        upk(op, o[c], o[c + 8]);
    }

    // ---- stores: out_X row (64B) then alphas (8B) ----
    const int tglob = tbase + tl;
    float4* outX = (float4*)(out + ((size_t)b * T_ + tglob) * 16);
    outX[0] = make_float4(o[0],  o[1],  o[2],  o[3]);
    outX[1] = make_float4(o[4],  o[5],  o[6],  o[7]);
    outX[2] = make_float4(o[8],  o[9],  o[10], o[11]);
    outX[3] = make_float4(o[12], o[13], o[14], o[15]);
    float2* outA = (float2*)(out + (size_t)B_ * T_ * 16 + ((size_t)b * T_ + tglob) * 2);
    *outA = make_float2(a0, a1);
}

extern "C" void kernel_launch(void* const* d_in, const int* in_sizes, int n_in,
                              void* d_out, int out_size)
{
    const float* x      = (const float*)d_in[0];
    const float* conv_w = (const float*)d_in[1];
    const float* conv_b = (const float*)d_in[2];
    const float* w1     = (const float*)d_in[3];
    const float* b1     = (const float*)d_in[4];
    const float* w2     = (const float*)d_in[5];
    const float* b2     = (const float*)d_in[6];
    const float* ln_g   = (const float*)d_in[7];
    const float* ln_b   = (const float*)d_in[8];

    dim3 grid(T_ / TILE, B_);
    bimanual_kernel<<<grid, 256>>>(x, conv_w, conv_b, w1, b1, w2, b2, ln_g, ln_b,
                                   (float*)d_out);
}

// round 2
// speedup vs baseline: 1.0714x; 1.0714x over previous
#include <cuda_runtime.h>

#define B_      512
#define T_      4096
#define TILE    512
#define THREADS 128
#define ITEMS   4
#define XROW    9

typedef unsigned long long u64;

// ---- packed f32x2 helpers (PTX-only path on sm_103a; ptxas won't auto-fuse) ----
__device__ __forceinline__ u64 pk(float lo, float hi) {
    u64 r; asm("mov.b64 %0,{%1,%2};" : "=l"(r) : "f"(lo), "f"(hi)); return r;
}
__device__ __forceinline__ void upk(u64 v, float& lo, float& hi) {
    asm("mov.b64 {%0,%1},%2;" : "=f"(lo), "=f"(hi) : "l"(v));
}
__device__ __forceinline__ u64 ffma2(u64 a, u64 b, u64 c) {
    u64 d; asm("fma.rn.f32x2 %0,%1,%2,%3;" : "=l"(d) : "l"(a), "l"(b), "l"(c)); return d;
}
__device__ __forceinline__ u64 fmul2(u64 a, u64 b) {
    u64 d; asm("mul.rn.f32x2 %0,%1,%2;" : "=l"(d) : "l"(a), "l"(b)); return d;
}
__device__ __forceinline__ u64 fadd2(u64 a, u64 b) {
    u64 d; asm("add.rn.f32x2 %0,%1,%2;" : "=l"(d) : "l"(a), "l"(b)); return d;
}

__global__ __launch_bounds__(THREADS)
void bimanual_kernel(const float* __restrict__ x,
                     const float* __restrict__ conv_w, const float* __restrict__ conv_b,
                     const float* __restrict__ w1, const float* __restrict__ b1,
                     const float* __restrict__ w2, const float* __restrict__ b2,
                     const float* __restrict__ ln_g, const float* __restrict__ ln_b,
                     float* __restrict__ out)
{
    __shared__ __align__(16) u64   xs[(TILE + 2) * XROW];   // pair-interleaved x tile (72B rows)
    __shared__ __align__(16) u64   cwp[16 * 24];            // conv weights, (w,w) pairs, [oc][k][ic]
    __shared__ __align__(16) float w1s[512];                // w1 raw (32,16)
    __shared__ u64 cbp[16];                                 // conv bias pairs
    __shared__ u64 b1p[8];                                  // b1 as hidden-output pairs
    __shared__ u64 w2ps[16];                                // w2 row pairs (w2[h][0], w2[h][1])
    __shared__ u64 b2ps[1];
    __shared__ u64 gp[8], bp[8];                            // ln gamma/beta packed (c, c+8)

    const int tid   = threadIdx.x;
    const int b     = blockIdx.y;
    const int tbase = blockIdx.x * TILE;

    // ---- stage x tile (TILE + 2 halo rows; t<0 rows are the conv zero-padding) ----
    for (int tt = tid; tt < TILE + 2; tt += THREADS) {
        const int t = tbase - 2 + tt;
        u64* row = &xs[tt * XROW];
        if (t >= 0) {
            const float4* p = (const float4*)(x + ((size_t)b * T_ + t) * 16);
            float4 a = p[0], bq = p[1], c = p[2], d = p[3];
            row[0] = pk(a.x,  c.x); row[1] = pk(a.y,  c.y);
            row[2] = pk(a.z,  c.z); row[3] = pk(a.w,  c.w);
            row[4] = pk(bq.x, d.x); row[5] = pk(bq.y, d.y);
            row[6] = pk(bq.z, d.z); row[7] = pk(bq.w, d.w);
        } else {
            #pragma unroll
            for (int j = 0; j < 8; ++j) row[j] = 0ull;
        }
    }

    // ---- stage weights (pre-packed (w,w) for f32x2 where useful) ----
    for (int j = tid; j < 384; j += THREADS) {
        const int oc = j / 24, r = j % 24, ic = r / 3, k = r % 3;  // conv_w is (oc, ic, k)
        const float w = conv_w[j];
        cwp[oc * 24 + k * 8 + ic] = pk(w, w);
    }
    for (int j = tid; j < 512; j += THREADS) w1s[j] = w1[j];
    if (tid < 16) cbp[tid]  = pk(conv_b[tid], conv_b[tid]);
    if (tid < 8)  b1p[tid]  = pk(b1[2 * tid], b1[2 * tid + 1]);
    if (tid < 16) w2ps[tid] = pk(w2[2 * tid], w2[2 * tid + 1]);
    if (tid == 0) b2ps[0]   = pk(b2[0], b2[1]);
    if (tid < 8)  gp[tid]   = pk(ln_g[tid], ln_g[tid + 8]);
    if (tid < 8)  bp[tid]   = pk(ln_b[tid], ln_b[tid + 8]);
    __syncthreads();

    // ---- per-thread: ITEMS consecutive elements, window rows r0 .. r0+ITEMS+1 ----
    const int r0 = tid * ITEMS;

    u64 xp[ITEMS + 2][8];
    #pragma unroll
    for (int r = 0; r < ITEMS + 2; ++r) {
        const u64* row = &xs[(r0 + r) * XROW];
        #pragma unroll
        for (int ic = 0; ic < 8; ++ic) xp[r][ic] = row[ic];
    }

    // hidden accumulators: 8 packed output-pairs per element
    u64 hid[ITEMS][8];
    #pragma unroll
    for (int j = 0; j < 8; ++j) {
        const u64 bj = b1p[j];
        #pragma unroll
        for (int i = 0; i < ITEMS; ++i) hid[i][j] = bj;
    }

    // ---- fused conv(+ReLU) -> rank-1 MLP update, weights amortized over ITEMS ----
    #pragma unroll
    for (int oc = 0; oc < 16; ++oc) {
        u64 acc[ITEMS];
        {
            const u64 cb = cbp[oc];
            #pragma unroll
            for (int i = 0; i < ITEMS; ++i) acc[i] = cb;
        }
        #pragma unroll
        for (int k = 0; k < 3; ++k) {
            const ulonglong2* wp = (const ulonglong2*)&cwp[oc * 24 + k * 8];
            #pragma unroll
            for (int q = 0; q < 4; ++q) {
                const ulonglong2 wv = wp[q];          // LDS.128 = 2 packed weight pairs
                #pragma unroll
                for (int i = 0; i < ITEMS; ++i)
                    acc[i] = ffma2(xp[i + k][2 * q], wv.x, acc[i]);
                #pragma unroll
                for (int i = 0; i < ITEMS; ++i)
                    acc[i] = ffma2(xp[i + k][2 * q + 1], wv.y, acc[i]);
            }
        }
        // ReLU + broadcast-splat per element
        u64 vl[ITEMS], vr[ITEMS];
        #pragma unroll
        for (int i = 0; i < ITEMS; ++i) {
            float hl, hr; upk(acc[i], hl, hr);
            hl = fmaxf(hl, 0.f); hr = fmaxf(hr, 0.f);
            vl[i] = pk(hl, hl); vr[i] = pk(hr, hr);
        }
        // rank-1 update of hidden accs: hid += hl*w1[oc,:] + hr*w1[16+oc,:]
        const u64* wlr = (const u64*)&w1s[oc * 16];
        const u64* wrr = (const u64*)&w1s[(16 + oc) * 16];
        #pragma unroll
        for (int j = 0; j < 8; ++j) {
            const u64 wlj = wlr[j];
            const u64 wrj = wrr[j];
            #pragma unroll
            for (int i = 0; i < ITEMS; ++i)
                hid[i][j] = ffma2(vl[i], wlj, ffma2(vr[i], wrj, hid[i][j]));
        }
    }

    // ---- logits + softmax(2) per element (w2 hoisted into regs, reused ITEMS x) ----
    u64 w2r[16];
    #pragma unroll
    for (int h = 0; h < 16; ++h) w2r[h] = w2ps[h];
    const u64 b2v = b2ps[0];

    float a0v[ITEMS], a1v[ITEMS];
    #pragma unroll
    for (int i = 0; i < ITEMS; ++i) {
        u64 lacc = b2v;
        #pragma unroll
        for (int j = 0; j < 8; ++j) {
            float h0, h1; upk(hid[i][j], h0, h1);
            h0 = fmaxf(h0, 0.f); h1 = fmaxf(h1, 0.f);
            lacc = ffma2(pk(h0, h0), w2r[2 * j],     lacc);
            lacc = ffma2(pk(h1, h1), w2r[2 * j + 1], lacc);
        }
        float l0, l1; upk(lacc, l0, l1);
        const float e = __expf(l1 - l0);
        a0v[i] = 1.f / (1.f + e);
        a1v[i] = e * a0v[i];
    }

    // ---- gated residual + LayerNorm(16) + stores, per element ----
    #pragma unroll
    for (int i = 0; i < ITEMS; ++i) {
        const u64 sp = pk(1.f + a0v[i], 1.f + a1v[i]);   // y = x * (1 + alpha_side)
        u64 yp[8];
        u64 sum = pk(0.f, 0.f);
        #pragma unroll
        for (int c = 0; c < 8; ++c) { yp[c] = fmul2(xp[i + 2][c], sp); sum = fadd2(sum, yp[c]); }
        float sL, sR; upk(sum, sL, sR);
        const float mu   = (sL + sR) * 0.0625f;
        const u64   nmup = pk(-mu, -mu);
        u64 var2 = pk(0.f, 0.f);
        u64 dp[8];
        #pragma unroll
        for (int c = 0; c < 8; ++c) { dp[c] = fadd2(yp[c], nmup); var2 = ffma2(dp[c], dp[c], var2); }
        float vL, vR; upk(var2, vL, vR);
        const float rs  = rsqrtf((vL + vR) * 0.0625f + 1e-5f);
        const u64   rsp = pk(rs, rs);

        float o[16];
        #pragma unroll
        for (int c = 0; c < 8; ++c) {
            const u64 op = ffma2(fmul2(dp[c], rsp), gp[c], bp[c]);
            upk(op, o[c], o[c + 8]);
        }

        const int tglob = tbase + r0 + i;
        float4* outX = (float4*)(out + ((size_t)b * T_ + tglob) * 16);
        outX[0] = make_float4(o[0],  o[1],  o[2],  o[3]);
        outX[1] = make_float4(o[4],  o[5],  o[6],  o[7]);
        outX[2] = make_float4(o[8],  o[9],  o[10], o[11]);
        outX[3] = make_float4(o[12], o[13], o[14], o[15]);
        float2* outA = (float2*)(out + (size_t)B_ * T_ * 16 + ((size_t)b * T_ + tglob) * 2);
        *outA = make_float2(a0v[i], a1v[i]);
    }
}

extern "C" void kernel_launch(void* const* d_in, const int* in_sizes, int n_in,
                              void* d_out, int out_size)
{
    const float* x      = (const float*)d_in[0];
    const float* conv_w = (const float*)d_in[1];
    const float* conv_b = (const float*)d_in[2];
    const float* w1     = (const float*)d_in[3];
    const float* b1     = (const float*)d_in[4];
    const float* w2     = (const float*)d_in[5];
    const float* b2     = (const float*)d_in[6];
    const float* ln_g   = (const float*)d_in[7];
    const float* ln_b   = (const float*)d_in[8];

    dim3 grid(T_ / TILE, B_);
    bimanual_kernel<<<grid, THREADS>>>(x, conv_w, conv_b, w1, b1, w2, b2, ln_g, ln_b,
                                       (float*)d_out);
}

// round 3
// speedup vs baseline: 1.2501x; 1.1668x over previous
#include <cuda_runtime.h>

#define B_      512
#define T_      4096
#define THREADS 128
#define ITEMS   2
#define TILE    (THREADS * ITEMS)   // 256
#define XROW    9

typedef unsigned long long u64;

// ---- packed f32x2 helpers (PTX-only path on sm_103a; ptxas won't auto-fuse) ----
__device__ __forceinline__ u64 pk(float lo, float hi) {
    u64 r; asm("mov.b64 %0,{%1,%2};" : "=l"(r) : "f"(lo), "f"(hi)); return r;
}
__device__ __forceinline__ void upk(u64 v, float& lo, float& hi) {
    asm("mov.b64 {%0,%1},%2;" : "=f"(lo), "=f"(hi) : "l"(v));
}
__device__ __forceinline__ u64 ffma2(u64 a, u64 b, u64 c) {
    u64 d; asm("fma.rn.f32x2 %0,%1,%2,%3;" : "=l"(d) : "l"(a), "l"(b), "l"(c)); return d;
}
__device__ __forceinline__ u64 fmul2(u64 a, u64 b) {
    u64 d; asm("mul.rn.f32x2 %0,%1,%2;" : "=l"(d) : "l"(a), "l"(b)); return d;
}
__device__ __forceinline__ u64 fadd2(u64 a, u64 b) {
    u64 d; asm("add.rn.f32x2 %0,%1,%2;" : "=l"(d) : "l"(a), "l"(b)); return d;
}

__global__ __launch_bounds__(THREADS, 4)
void bimanual_kernel(const float* __restrict__ x,
                     const float* __restrict__ conv_w, const float* __restrict__ conv_b,
                     const float* __restrict__ w1, const float* __restrict__ b1,
                     const float* __restrict__ w2, const float* __restrict__ b2,
                     const float* __restrict__ ln_g, const float* __restrict__ ln_b,
                     float* __restrict__ out)
{
    __shared__ __align__(16) u64   xs[(TILE + 2) * XROW];   // pair-interleaved x tile (72B rows)
    __shared__ __align__(16) u64   cwp[16 * 24];            // conv weights, (w,w) pairs, [oc][k][ic]
    __shared__ __align__(16) float w1s[512];                // w1 raw (32,16)
    __shared__ __align__(16) u64   w2ps[16];                // w2 row pairs (w2[h][0], w2[h][1])
    __shared__ u64 cbp[16];                                 // conv bias pairs
    __shared__ u64 b1p[8];                                  // b1 as hidden-output pairs
    __shared__ u64 b2ps[1];
    __shared__ u64 gp[8], bp[8];                            // ln gamma/beta packed (c, c+8)

    const int tid   = threadIdx.x;
    const int b     = blockIdx.y;
    const int tbase = blockIdx.x * TILE;

    // ---- stage x tile (TILE + 2 halo rows; t<0 rows are the conv zero-padding) ----
    for (int tt = tid; tt < TILE + 2; tt += THREADS) {
        const int t = tbase - 2 + tt;
        u64* row = &xs[tt * XROW];
        if (t >= 0) {
            const float4* p = (const float4*)(x + ((size_t)b * T_ + t) * 16);
            float4 a = p[0], bq = p[1], c = p[2], d = p[3];
            row[0] = pk(a.x,  c.x); row[1] = pk(a.y,  c.y);
            row[2] = pk(a.z,  c.z); row[3] = pk(a.w,  c.w);
            row[4] = pk(bq.x, d.x); row[5] = pk(bq.y, d.y);
            row[6] = pk(bq.z, d.z); row[7] = pk(bq.w, d.w);
        } else {
            #pragma unroll
            for (int j = 0; j < 8; ++j) row[j] = 0ull;
        }
    }

    // ---- stage weights (pre-packed (w,w) for f32x2 where useful) ----
    for (int j = tid; j < 384; j += THREADS) {
        const int oc = j / 24, r = j % 24, ic = r / 3, k = r % 3;  // conv_w is (oc, ic, k)
        const float w = conv_w[j];
        cwp[oc * 24 + k * 8 + ic] = pk(w, w);
    }
    for (int j = tid; j < 512; j += THREADS) w1s[j] = w1[j];
    if (tid < 16) cbp[tid]  = pk(conv_b[tid], conv_b[tid]);
    if (tid < 8)  b1p[tid]  = pk(b1[2 * tid], b1[2 * tid + 1]);
    if (tid < 16) w2ps[tid] = pk(w2[2 * tid], w2[2 * tid + 1]);
    if (tid == 0) b2ps[0]   = pk(b2[0], b2[1]);
    if (tid < 8)  gp[tid]   = pk(ln_g[tid], ln_g[tid + 8]);
    if (tid < 8)  bp[tid]   = pk(ln_b[tid], ln_b[tid + 8]);
    __syncthreads();

    // ---- per-thread: ITEMS consecutive elements, window rows r0 .. r0+ITEMS+1 ----
    const int r0 = tid * ITEMS;

    // hidden accumulators: 8 packed output-pairs per element
    u64 hid[ITEMS][8];
    #pragma unroll
    for (int j = 0; j < 8; ++j) {
        const u64 bj = b1p[j];
        #pragma unroll
        for (int i = 0; i < ITEMS; ++i) hid[i][j] = bj;
    }

    // Scope the x window so it is dead after the conv loop (register pressure).
    {
        u64 xp[ITEMS + 2][8];
        #pragma unroll
        for (int r = 0; r < ITEMS + 2; ++r) {
            const u64* row = &xs[(r0 + r) * XROW];
            #pragma unroll
            for (int ic = 0; ic < 8; ++ic) xp[r][ic] = row[ic];
        }

        // ---- fused conv(+ReLU) -> rank-1 MLP update, weights amortized over ITEMS ----
        #pragma unroll
        for (int oc = 0; oc < 16; ++oc) {
            u64 acc[ITEMS];
            {
                const u64 cb = cbp[oc];
                #pragma unroll
                for (int i = 0; i < ITEMS; ++i) acc[i] = cb;
            }
            #pragma unroll
            for (int k = 0; k < 3; ++k) {
                const ulonglong2* wp = (const ulonglong2*)&cwp[oc * 24 + k * 8];
                #pragma unroll
                for (int q = 0; q < 4; ++q) {
                    const ulonglong2 wv = wp[q];      // LDS.128 = 2 packed weight pairs
                    #pragma unroll
                    for (int i = 0; i < ITEMS; ++i)
                        acc[i] = ffma2(xp[i + k][2 * q], wv.x, acc[i]);
                    #pragma unroll
                    for (int i = 0; i < ITEMS; ++i)
                        acc[i] = ffma2(xp[i + k][2 * q + 1], wv.y, acc[i]);
                }
            }
            // ReLU + broadcast-splat per element
            u64 vl[ITEMS], vr[ITEMS];
            #pragma unroll
            for (int i = 0; i < ITEMS; ++i) {
                float hl, hr; upk(acc[i], hl, hr);
                hl = fmaxf(hl, 0.f); hr = fmaxf(hr, 0.f);
                vl[i] = pk(hl, hl); vr[i] = pk(hr, hr);
            }
            // rank-1 update of hidden accs: hid += hl*w1[oc,:] + hr*w1[16+oc,:]
            const ulonglong2* wlr = (const ulonglong2*)&w1s[oc * 16];
            const ulonglong2* wrr = (const ulonglong2*)&w1s[(16 + oc) * 16];
            #pragma unroll
            for (int q = 0; q < 4; ++q) {
                const ulonglong2 wl = wlr[q];
                const ulonglong2 wr = wrr[q];
                #pragma unroll
                for (int i = 0; i < ITEMS; ++i) {
                    hid[i][2 * q]     = ffma2(vl[i], wl.x, ffma2(vr[i], wr.x, hid[i][2 * q]));
                    hid[i][2 * q + 1] = ffma2(vl[i], wl.y, ffma2(vr[i], wr.y, hid[i][2 * q + 1]));
                }
            }
        }
    } // xp dies here

    // ---- logits + softmax(2) per element (w2 via broadcast LDS.128) ----
    float a0v[ITEMS], a1v[ITEMS];
    #pragma unroll
    for (int i = 0; i < ITEMS; ++i) {
        u64 lacc = b2ps[0];
        const ulonglong2* w2q = (const ulonglong2*)w2ps;
        #pragma unroll
        for (int j = 0; j < 8; ++j) {
            float h0, h1; upk(hid[i][j], h0, h1);
            h0 = fmaxf(h0, 0.f); h1 = fmaxf(h1, 0.f);
            const ulonglong2 wv = w2q[j];
            lacc = ffma2(pk(h0, h0), wv.x, lacc);
            lacc = ffma2(pk(h1, h1), wv.y, lacc);
        }
        float l0, l1; upk(lacc, l0, l1);
        const float e = __expf(l1 - l0);
        a0v[i] = 1.f / (1.f + e);
        a1v[i] = e * a0v[i];
    }

    // ---- gated residual + LayerNorm(16) + stores (x reloaded from smem) ----
    #pragma unroll
    for (int i = 0; i < ITEMS; ++i) {
        const u64* xrow = &xs[(r0 + i + 2) * XROW];
        const u64 sp = pk(1.f + a0v[i], 1.f + a1v[i]);   // y = x * (1 + alpha_side)
        u64 yp[8];
        u64 sum = pk(0.f, 0.f);
        #pragma unroll
        for (int c = 0; c < 8; ++c) { yp[c] = fmul2(xrow[c], sp); sum = fadd2(sum, yp[c]); }
        float sL, sR; upk(sum, sL, sR);
        const float mu   = (sL + sR) * 0.0625f;
        const u64   nmup = pk(-mu, -mu);
        u64 var2 = pk(0.f, 0.f);
        u64 dp[8];
        #pragma unroll
        for (int c = 0; c < 8; ++c) { dp[c] = fadd2(yp[c], nmup); var2 = ffma2(dp[c], dp[c], var2); }
        float vL, vR; upk(var2, vL, vR);
        const float rs  = rsqrtf((vL + vR) * 0.0625f + 1e-5f);
        const u64   rsp = pk(rs, rs);

        float o[16];
        #pragma unroll
        for (int c = 0; c < 8; ++c) {
            const u64 op = ffma2(fmul2(dp[c], rsp), gp[c], bp[c]);
            upk(op, o[c], o[c + 8]);
        }

        const int tglob = tbase + r0 + i;
        float4* outX = (float4*)(out + ((size_t)b * T_ + tglob) * 16);
        outX[0] = make_float4(o[0],  o[1],  o[2],  o[3]);
        outX[1] = make_float4(o[4],  o[5],  o[6],  o[7]);
        outX[2] = make_float4(o[8],  o[9],  o[10], o[11]);
        outX[3] = make_float4(o[12], o[13], o[14], o[15]);
        float2* outA = (float2*)(out + (size_t)B_ * T_ * 16 + ((size_t)b * T_ + tglob) * 2);
        *outA = make_float2(a0v[i], a1v[i]);
    }
}

extern "C" void kernel_launch(void* const* d_in, const int* in_sizes, int n_in,
                              void* d_out, int out_size)
{
    const float* x      = (const float*)d_in[0];
    const float* conv_w = (const float*)d_in[1];
    const float* conv_b = (const float*)d_in[2];
    const float* w1     = (const float*)d_in[3];
    const float* b1     = (const float*)d_in[4];
    const float* w2     = (const float*)d_in[5];
    const float* b2     = (const float*)d_in[6];
    const float* ln_g   = (const float*)d_in[7];
    const float* ln_b   = (const float*)d_in[8];

    dim3 grid(T_ / TILE, B_);
    bimanual_kernel<<<grid, THREADS>>>(x, conv_w, conv_b, w1, b1, w2, b2, ln_g, ln_b,
                                       (float*)d_out);
}

// round 4
// speedup vs baseline: 1.3266x; 1.0612x over previous
#include <cuda_runtime.h>

#define B_      512
#define T_      4096
#define THREADS 128
#define ITEMS   3
#define TILE    (THREADS * ITEMS)   // 384 (ragged last block: 4096 = 10*384 + 256)
#define XROW    11                  // lane dist = 3*11=33 u64 == 2 words (mod 32): conflict-free

typedef unsigned long long u64;

// ---- packed f32x2 helpers (PTX-only path on sm_103a; ptxas won't auto-fuse) ----
__device__ __forceinline__ u64 pk(float lo, float hi) {
    u64 r; asm("mov.b64 %0,{%1,%2};" : "=l"(r) : "f"(lo), "f"(hi)); return r;
}
__device__ __forceinline__ void upk(u64 v, float& lo, float& hi) {
    asm("mov.b64 {%0,%1},%2;" : "=f"(lo), "=f"(hi) : "l"(v));
}
__device__ __forceinline__ u64 ffma2(u64 a, u64 b, u64 c) {
    u64 d; asm("fma.rn.f32x2 %0,%1,%2,%3;" : "=l"(d) : "l"(a), "l"(b), "l"(c)); return d;
}
__device__ __forceinline__ u64 fmul2(u64 a, u64 b) {
    u64 d; asm("mul.rn.f32x2 %0,%1,%2;" : "=l"(d) : "l"(a), "l"(b)); return d;
}
__device__ __forceinline__ u64 fadd2(u64 a, u64 b) {
    u64 d; asm("add.rn.f32x2 %0,%1,%2;" : "=l"(d) : "l"(a), "l"(b)); return d;
}

__global__ __launch_bounds__(THREADS, 3)
void bimanual_kernel(const float* __restrict__ x,
                     const float* __restrict__ conv_w, const float* __restrict__ conv_b,
                     const float* __restrict__ w1, const float* __restrict__ b1,
                     const float* __restrict__ w2, const float* __restrict__ b2,
                     const float* __restrict__ ln_g, const float* __restrict__ ln_b,
                     float* __restrict__ out)
{
    __shared__ __align__(16) u64   xs[(TILE + 2) * XROW];   // pair-interleaved x tile (88B rows)
    __shared__ __align__(16) u64   cwp[16 * 24];            // conv weights, (w,w) pairs, [oc][k][ic]
    __shared__ __align__(16) float w1s[512];                // w1 raw (32,16)
    __shared__ __align__(16) u64   w2ps[16];                // w2 row pairs (w2[h][0], w2[h][1])
    __shared__ u64 cbp[16];                                 // conv bias pairs
    __shared__ u64 b1p[8];                                  // b1 as hidden-output pairs
    __shared__ u64 b2ps[1];
    __shared__ u64 gp[8], bp[8];                            // ln gamma/beta packed (c, c+8)

    const int tid   = threadIdx.x;
    const int b     = blockIdx.y;
    const int tbase = blockIdx.x * TILE;

    // ---- stage x tile (TILE + 2 halo rows; t<0 or t>=T_ rows are zeros) ----
    for (int tt = tid; tt < TILE + 2; tt += THREADS) {
        const int t = tbase - 2 + tt;
        u64* row = &xs[tt * XROW];
        if (t >= 0 && t < T_) {
            const float4* p = (const float4*)(x + ((size_t)b * T_ + t) * 16);
            float4 a = p[0], bq = p[1], c = p[2], d = p[3];
            row[0] = pk(a.x,  c.x); row[1] = pk(a.y,  c.y);
            row[2] = pk(a.z,  c.z); row[3] = pk(a.w,  c.w);
            row[4] = pk(bq.x, d.x); row[5] = pk(bq.y, d.y);
            row[6] = pk(bq.z, d.z); row[7] = pk(bq.w, d.w);
        } else {
            #pragma unroll
            for (int j = 0; j < 8; ++j) row[j] = 0ull;
        }
    }

    // ---- stage weights (pre-packed (w,w) for f32x2 where useful) ----
    for (int j = tid; j < 384; j += THREADS) {
        const int oc = j / 24, r = j % 24, ic = r / 3, k = r % 3;  // conv_w is (oc, ic, k)
        const float w = conv_w[j];
        cwp[oc * 24 + k * 8 + ic] = pk(w, w);
    }
    for (int j = tid; j < 512; j += THREADS) w1s[j] = w1[j];
    if (tid < 16) cbp[tid]  = pk(conv_b[tid], conv_b[tid]);
    if (tid < 8)  b1p[tid]  = pk(b1[2 * tid], b1[2 * tid + 1]);
    if (tid < 16) w2ps[tid] = pk(w2[2 * tid], w2[2 * tid + 1]);
    if (tid == 0) b2ps[0]   = pk(b2[0], b2[1]);
    if (tid < 8)  gp[tid]   = pk(ln_g[tid], ln_g[tid + 8]);
    if (tid < 8)  bp[tid]   = pk(ln_b[tid], ln_b[tid + 8]);
    __syncthreads();

    // ---- per-thread: ITEMS consecutive elements, window rows r0 .. r0+ITEMS+1 ----
    const int r0 = tid * ITEMS;

    // hidden accumulators: 8 packed output-pairs per element
    u64 hid[ITEMS][8];
    #pragma unroll
    for (int j = 0; j < 8; ++j) {
        const u64 bj = b1p[j];
        #pragma unroll
        for (int i = 0; i < ITEMS; ++i) hid[i][j] = bj;
    }

    // Scope the x window so it is dead after the conv loop (register pressure).
    {
        u64 xp[ITEMS + 2][8];
        #pragma unroll
        for (int r = 0; r < ITEMS + 2; ++r) {
            const u64* row = &xs[(r0 + r) * XROW];
            #pragma unroll
            for (int ic = 0; ic < 8; ++ic) xp[r][ic] = row[ic];
        }

        // ---- fused conv(+ReLU) -> rank-1 MLP update, weights amortized over ITEMS ----
        #pragma unroll
        for (int oc = 0; oc < 16; ++oc) {
            u64 acc[ITEMS];
            {
                const u64 cb = cbp[oc];
                #pragma unroll
                for (int i = 0; i < ITEMS; ++i) acc[i] = cb;
            }
            #pragma unroll
            for (int k = 0; k < 3; ++k) {
                const ulonglong2* wp = (const ulonglong2*)&cwp[oc * 24 + k * 8];
                #pragma unroll
                for (int q = 0; q < 4; ++q) {
                    const ulonglong2 wv = wp[q];      // LDS.128 = 2 packed weight pairs
                    #pragma unroll
                    for (int i = 0; i < ITEMS; ++i)
                        acc[i] = ffma2(xp[i + k][2 * q], wv.x, acc[i]);
                    #pragma unroll
                    for (int i = 0; i < ITEMS; ++i)
                        acc[i] = ffma2(xp[i + k][2 * q + 1], wv.y, acc[i]);
                }
            }
            // ReLU + broadcast-splat per element
            u64 vl[ITEMS], vr[ITEMS];
            #pragma unroll
            for (int i = 0; i < ITEMS; ++i) {
                float hl, hr; upk(acc[i], hl, hr);
                hl = fmaxf(hl, 0.f); hr = fmaxf(hr, 0.f);
                vl[i] = pk(hl, hl); vr[i] = pk(hr, hr);
            }
            // rank-1 update of hidden accs: hid += hl*w1[oc,:] + hr*w1[16+oc,:]
            const ulonglong2* wlr = (const ulonglong2*)&w1s[oc * 16];
            const ulonglong2* wrr = (const ulonglong2*)&w1s[(16 + oc) * 16];
            #pragma unroll
            for (int q = 0; q < 4; ++q) {
                const ulonglong2 wl = wlr[q];
                const ulonglong2 wr = wrr[q];
                #pragma unroll
                for (int i = 0; i < ITEMS; ++i) {
                    hid[i][2 * q]     = ffma2(vl[i], wl.x, ffma2(vr[i], wr.x, hid[i][2 * q]));
                    hid[i][2 * q + 1] = ffma2(vl[i], wl.y, ffma2(vr[i], wr.y, hid[i][2 * q + 1]));
                }
            }
        }
    } // xp dies here

    // ---- logits + softmax(2): j outer so w2 LDS amortizes over items ----
    u64 lacc[ITEMS];
    #pragma unroll
    for (int i = 0; i < ITEMS; ++i) lacc[i] = b2ps[0];
    {
        const ulonglong2* w2q = (const ulonglong2*)w2ps;
        #pragma unroll
        for (int j = 0; j < 8; ++j) {
            const ulonglong2 wv = w2q[j];
            #pragma unroll
            for (int i = 0; i < ITEMS; ++i) {
                float h0, h1; upk(hid[i][j], h0, h1);
                h0 = fmaxf(h0, 0.f); h1 = fmaxf(h1, 0.f);
                lacc[i] = ffma2(pk(h0, h0), wv.x, lacc[i]);
                lacc[i] = ffma2(pk(h1, h1), wv.y, lacc[i]);
            }
        }
    }
    float a0v[ITEMS], a1v[ITEMS];
    #pragma unroll
    for (int i = 0; i < ITEMS; ++i) {
        float l0, l1; upk(lacc[i], l0, l1);
        const float e = __expf(l1 - l0);
        a0v[i] = 1.f / (1.f + e);
        a1v[i] = e * a0v[i];
    }

    // ---- gated residual + LayerNorm(16) + stores (x reloaded from smem) ----
    #pragma unroll
    for (int i = 0; i < ITEMS; ++i) {
        const int tglob = tbase + r0 + i;
        if (tglob >= T_) break;                            // ragged last block
        const u64* xrow = &xs[(r0 + i + 2) * XROW];
        const u64 sp = pk(1.f + a0v[i], 1.f + a1v[i]);     // y = x * (1 + alpha_side)
        u64 yp[8];
        u64 sum = pk(0.f, 0.f);
        #pragma unroll
        for (int c = 0; c < 8; ++c) { yp[c] = fmul2(xrow[c], sp); sum = fadd2(sum, yp[c]); }
        float sL, sR; upk(sum, sL, sR);
        const float mu   = (sL + sR) * 0.0625f;
        const u64   nmup = pk(-mu, -mu);
        u64 var2 = pk(0.f, 0.f);
        u64 dp[8];
        #pragma unroll
        for (int c = 0; c < 8; ++c) { dp[c] = fadd2(yp[c], nmup); var2 = ffma2(dp[c], dp[c], var2); }
        float vL, vR; upk(var2, vL, vR);
        const float rs  = rsqrtf((vL + vR) * 0.0625f + 1e-5f);
        const u64   rsp = pk(rs, rs);

        float o[16];
        #pragma unroll
        for (int c = 0; c < 8; ++c) {
            const u64 op = ffma2(fmul2(dp[c], rsp), gp[c], bp[c]);
            upk(op, o[c], o[c + 8]);
        }

        float4* outX = (float4*)(out + ((size_t)b * T_ + tglob) * 16);
        outX[0] = make_float4(o[0],  o[1],  o[2],  o[3]);
        outX[1] = make_float4(o[4],  o[5],  o[6],  o[7]);
        outX[2] = make_float4(o[8],  o[9],  o[10], o[11]);
        outX[3] = make_float4(o[12], o[13], o[14], o[15]);
        float2* outA = (float2*)(out + (size_t)B_ * T_ * 16 + ((size_t)b * T_ + tglob) * 2);
        *outA = make_float2(a0v[i], a1v[i]);
    }
}

extern "C" void kernel_launch(void* const* d_in, const int* in_sizes, int n_in,
                              void* d_out, int out_size)
{
    const float* x      = (const float*)d_in[0];
    const float* conv_w = (const float*)d_in[1];
    const float* conv_b = (const float*)d_in[2];
    const float* w1     = (const float*)d_in[3];
    const float* b1     = (const float*)d_in[4];
    const float* w2     = (const float*)d_in[5];
    const float* b2     = (const float*)d_in[6];
    const float* ln_g   = (const float*)d_in[7];
    const float* ln_b   = (const float*)d_in[8];

    dim3 grid((T_ + TILE - 1) / TILE, B_);
    bimanual_kernel<<<grid, THREADS>>>(x, conv_w, conv_b, w1, b1, w2, b2, ln_g, ln_b,
                                       (float*)d_out);
}

// round 5
// speedup vs baseline: 1.4261x; 1.0750x over previous
#include <cuda_runtime.h>

#define B_      512
#define T_      4096
#define THREADS 128
#define ITEMS   3
#define TILE    (THREADS * ITEMS)   // 384 (ragged last block: 4096 = 10*384 + 256)
#define XROW    11                  // lane dist 33 u64: conflict-free LDS.64 phases

typedef unsigned long long u64;

// ---- packed f32x2 helpers (PTX-only path on sm_103a; ptxas won't auto-fuse) ----
__device__ __forceinline__ u64 pk(float lo, float hi) {
    u64 r; asm("mov.b64 %0,{%1,%2};" : "=l"(r) : "f"(lo), "f"(hi)); return r;
}
__device__ __forceinline__ void upk(u64 v, float& lo, float& hi) {
    asm("mov.b64 {%0,%1},%2;" : "=f"(lo), "=f"(hi) : "l"(v));
}
__device__ __forceinline__ u64 ffma2(u64 a, u64 b, u64 c) {
    u64 d; asm("fma.rn.f32x2 %0,%1,%2,%3;" : "=l"(d) : "l"(a), "l"(b), "l"(c)); return d;
}
__device__ __forceinline__ u64 fmul2(u64 a, u64 b) {
    u64 d; asm("mul.rn.f32x2 %0,%1,%2;" : "=l"(d) : "l"(a), "l"(b)); return d;
}
__device__ __forceinline__ u64 fadd2(u64 a, u64 b) {
    u64 d; asm("add.rn.f32x2 %0,%1,%2;" : "=l"(d) : "l"(a), "l"(b)); return d;
}

// ---- all weights, pre-packed for f32x2, in constant memory (separate LDC port) ----
struct __align__(16) Wts {
    u64 cw[384];   // conv weights (w,w) pairs, [oc][k][ic]
    u64 w1[256];   // w1 as hidden-output pairs: w1[f][j] = (w1[f,2j], w1[f,2j+1])
    u64 w2[16];    // w2 row pairs (w2[h][0], w2[h][1])
    u64 cb[16];    // conv bias (b,b)
    u64 b1[8];     // b1 output pairs
    u64 b2[2];     // (b2[0], b2[1]) + pad
    u64 g[8];      // ln gamma packed (c, c+8)
    u64 bb[8];     // ln beta  packed (c, c+8)
};
__constant__ Wts cW;
__device__   Wts dStage;

__global__ void prep_kernel(const float* __restrict__ conv_w, const float* __restrict__ conv_b,
                            const float* __restrict__ w1,     const float* __restrict__ b1,
                            const float* __restrict__ w2,     const float* __restrict__ b2,
                            const float* __restrict__ ln_g,   const float* __restrict__ ln_b)
{
    const int tid = threadIdx.x;
    for (int j = tid; j < 384; j += 128) {
        const int oc = j / 24, r = j % 24, ic = r / 3, k = r % 3;   // conv_w is (oc, ic, k)
        const float w = conv_w[j];
        dStage.cw[oc * 24 + k * 8 + ic] = pk(w, w);
    }
    for (int j = tid; j < 256; j += 128) {
        const int f = j / 8, q = j % 8;
        dStage.w1[j] = pk(w1[f * 16 + 2 * q], w1[f * 16 + 2 * q + 1]);
    }
    if (tid < 16) dStage.w2[tid] = pk(w2[2 * tid], w2[2 * tid + 1]);
    if (tid < 16) dStage.cb[tid] = pk(conv_b[tid], conv_b[tid]);
    if (tid < 8)  dStage.b1[tid] = pk(b1[2 * tid], b1[2 * tid + 1]);
    if (tid == 0) { dStage.b2[0] = pk(b2[0], b2[1]); dStage.b2[1] = 0ull; }
    if (tid < 8)  dStage.g[tid]  = pk(ln_g[tid], ln_g[tid + 8]);
    if (tid < 8)  dStage.bb[tid] = pk(ln_b[tid], ln_b[tid + 8]);
}

__global__ __launch_bounds__(THREADS, 3)
void bimanual_kernel(const float* __restrict__ x, float* __restrict__ out)
{
    __shared__ __align__(16) u64 xs[(TILE + 2) * XROW];   // pair-interleaved x tile

    const int tid   = threadIdx.x;
    const int b     = blockIdx.y;
    const int tbase = blockIdx.x * TILE;

    // ---- stage x tile (TILE + 2 halo rows; t<0 or t>=T_ rows are zeros) ----
    for (int tt = tid; tt < TILE + 2; tt += THREADS) {
        const int t = tbase - 2 + tt;
        u64* row = &xs[tt * XROW];
        if (t >= 0 && t < T_) {
            const float4* p = (const float4*)(x + ((size_t)b * T_ + t) * 16);
            float4 a = p[0], bq = p[1], c = p[2], d = p[3];
            row[0] = pk(a.x,  c.x); row[1] = pk(a.y,  c.y);
            row[2] = pk(a.z,  c.z); row[3] = pk(a.w,  c.w);
            row[4] = pk(bq.x, d.x); row[5] = pk(bq.y, d.y);
            row[6] = pk(bq.z, d.z); row[7] = pk(bq.w, d.w);
        } else {
            #pragma unroll
            for (int j = 0; j < 8; ++j) row[j] = 0ull;
        }
    }
    __syncthreads();

    // ---- per-thread: ITEMS consecutive elements, window rows r0 .. r0+ITEMS+1 ----
    const int r0 = tid * ITEMS;

    // hidden accumulators: 8 packed output-pairs per element
    u64 hid[ITEMS][8];
    #pragma unroll
    for (int j = 0; j < 8; ++j) {
        const u64 bj = cW.b1[j];
        #pragma unroll
        for (int i = 0; i < ITEMS; ++i) hid[i][j] = bj;
    }

    // Scope the x window so it is dead after the conv loop (register pressure).
    {
        u64 xp[ITEMS + 2][8];
        #pragma unroll
        for (int r = 0; r < ITEMS + 2; ++r) {
            const u64* row = &xs[(r0 + r) * XROW];
            #pragma unroll
            for (int ic = 0; ic < 8; ++ic) xp[r][ic] = row[ic];
        }

        // ---- fused conv(+ReLU) -> rank-1 MLP update; weights via constant port ----
        #pragma unroll
        for (int oc = 0; oc < 16; ++oc) {
            u64 acc[ITEMS];
            {
                const u64 cb = cW.cb[oc];
                #pragma unroll
                for (int i = 0; i < ITEMS; ++i) acc[i] = cb;
            }
            #pragma unroll
            for (int k = 0; k < 3; ++k) {
                const ulonglong2* wp = (const ulonglong2*)&cW.cw[oc * 24 + k * 8];
                #pragma unroll
                for (int q = 0; q < 4; ++q) {
                    const ulonglong2 wv = wp[q];      // LDC.128 = 2 packed weight pairs
                    #pragma unroll
                    for (int i = 0; i < ITEMS; ++i)
                        acc[i] = ffma2(xp[i + k][2 * q], wv.x, acc[i]);
                    #pragma unroll
                    for (int i = 0; i < ITEMS; ++i)
                        acc[i] = ffma2(xp[i + k][2 * q + 1], wv.y, acc[i]);
                }
            }
            // ReLU + broadcast-splat per element
            u64 vl[ITEMS], vr[ITEMS];
            #pragma unroll
            for (int i = 0; i < ITEMS; ++i) {
                float hl, hr; upk(acc[i], hl, hr);
                hl = fmaxf(hl, 0.f); hr = fmaxf(hr, 0.f);
                vl[i] = pk(hl, hl); vr[i] = pk(hr, hr);
            }
            // rank-1 update of hidden accs: hid += hl*w1[oc,:] + hr*w1[16+oc,:]
            const ulonglong2* wlr = (const ulonglong2*)&cW.w1[oc * 8];
            const ulonglong2* wrr = (const ulonglong2*)&cW.w1[(16 + oc) * 8];
            #pragma unroll
            for (int q = 0; q < 4; ++q) {
                const ulonglong2 wl = wlr[q];
                const ulonglong2 wr = wrr[q];
                #pragma unroll
                for (int i = 0; i < ITEMS; ++i) {
                    hid[i][2 * q]     = ffma2(vl[i], wl.x, ffma2(vr[i], wr.x, hid[i][2 * q]));
                    hid[i][2 * q + 1] = ffma2(vl[i], wl.y, ffma2(vr[i], wr.y, hid[i][2 * q + 1]));
                }
            }
        }
    } // xp dies here

    // ---- logits + softmax(2): j outer so w2 LDC amortizes over items ----
    u64 lacc[ITEMS];
    {
        const u64 b2v = cW.b2[0];
        #pragma unroll
        for (int i = 0; i < ITEMS; ++i) lacc[i] = b2v;
        const ulonglong2* w2q = (const ulonglong2*)cW.w2;
        #pragma unroll
        for (int j = 0; j < 8; ++j) {
            const ulonglong2 wv = w2q[j];
            #pragma unroll
            for (int i = 0; i < ITEMS; ++i) {
                float h0, h1; upk(hid[i][j], h0, h1);
                h0 = fmaxf(h0, 0.f); h1 = fmaxf(h1, 0.f);
                lacc[i] = ffma2(pk(h0, h0), wv.x, lacc[i]);
                lacc[i] = ffma2(pk(h1, h1), wv.y, lacc[i]);
            }
        }
    }
    float a0v[ITEMS], a1v[ITEMS];
    #pragma unroll
    for (int i = 0; i < ITEMS; ++i) {
        float l0, l1; upk(lacc[i], l0, l1);
        const float e = __expf(l1 - l0);
        a0v[i] = 1.f / (1.f + e);
        a1v[i] = e * a0v[i];
    }

    // ---- gated residual + LayerNorm(16) + stores (x reloaded from smem) ----
    #pragma unroll
    for (int i = 0; i < ITEMS; ++i) {
        const int tglob = tbase + r0 + i;
        if (tglob >= T_) break;                            // ragged last block
        const u64* xrow = &xs[(r0 + i + 2) * XROW];
        const u64 sp = pk(1.f + a0v[i], 1.f + a1v[i]);     // y = x * (1 + alpha_side)
        u64 yp[8];
        u64 sum = pk(0.f, 0.f);
        #pragma unroll
        for (int c = 0; c < 8; ++c) { yp[c] = fmul2(xrow[c], sp); sum = fadd2(sum, yp[c]); }
        float sL, sR; upk(sum, sL, sR);
        const float mu   = (sL + sR) * 0.0625f;
        const u64   nmup = pk(-mu, -mu);
        u64 var2 = pk(0.f, 0.f);
        u64 dp[8];
        #pragma unroll
        for (int c = 0; c < 8; ++c) { dp[c] = fadd2(yp[c], nmup); var2 = ffma2(dp[c], dp[c], var2); }
        float vL, vR; upk(var2, vL, vR);
        const float rs  = rsqrtf((vL + vR) * 0.0625f + 1e-5f);
        const u64   rsp = pk(rs, rs);

        float o[16];
        #pragma unroll
        for (int c = 0; c < 8; ++c) {
            const u64 op = ffma2(fmul2(dp[c], rsp), cW.g[c], cW.bb[c]);
            upk(op, o[c], o[c + 8]);
        }

        float4* outX = (float4*)(out + ((size_t)b * T_ + tglob) * 16);
        outX[0] = make_float4(o[0],  o[1],  o[2],  o[3]);
        outX[1] = make_float4(o[4],  o[5],  o[6],  o[7]);
        outX[2] = make_float4(o[8],  o[9],  o[10], o[11]);
        outX[3] = make_float4(o[12], o[13], o[14], o[15]);
        float2* outA = (float2*)(out + (size_t)B_ * T_ * 16 + ((size_t)b * T_ + tglob) * 2);
        *outA = make_float2(a0v[i], a1v[i]);
    }
}

extern "C" void kernel_launch(void* const* d_in, const int* in_sizes, int n_in,
                              void* d_out, int out_size)
{
    const float* x      = (const float*)d_in[0];
    const float* conv_w = (const float*)d_in[1];
    const float* conv_b = (const float*)d_in[2];
    const float* w1     = (const float*)d_in[3];
    const float* b1     = (const float*)d_in[4];
    const float* w2     = (const float*)d_in[5];
    const float* b2     = (const float*)d_in[6];
    const float* ln_g   = (const float*)d_in[7];
    const float* ln_b   = (const float*)d_in[8];

    // 1) pack weights into a device staging struct
    prep_kernel<<<1, 128>>>(conv_w, conv_b, w1, b1, w2, b2, ln_g, ln_b);

    // 2) D2D copy staging -> __constant__ (async, graph-capturable memcpy node)
    void* stage_ptr = nullptr;
    cudaGetSymbolAddress(&stage_ptr, dStage);
    cudaMemcpyToSymbolAsync(cW, stage_ptr, sizeof(Wts), 0, cudaMemcpyDeviceToDevice, 0);

    // 3) main kernel
    dim3 grid((T_ + TILE - 1) / TILE, B_);
    bimanual_kernel<<<grid, THREADS>>>(x, (float*)d_out);
}

// round 6
// speedup vs baseline: 1.7381x; 1.2188x over previous
#include <cuda_runtime.h>

#define B_      512
#define T_      4096
#define THREADS 128
#define ITEMS   2
#define TILE    (THREADS * ITEMS)   // 256 -> grid.x = 16 exact
#define XROW    9

typedef unsigned long long u64;

// ---- packed f32x2 helpers (PTX-only path on sm_103a; ptxas won't auto-fuse) ----
__device__ __forceinline__ u64 pk(float lo, float hi) {
    u64 r; asm("mov.b64 %0,{%1,%2};" : "=l"(r) : "f"(lo), "f"(hi)); return r;
}
__device__ __forceinline__ void upk(u64 v, float& lo, float& hi) {
    asm("mov.b64 {%0,%1},%2;" : "=f"(lo), "=f"(hi) : "l"(v));
}
__device__ __forceinline__ u64 ffma2(u64 a, u64 b, u64 c) {
    u64 d; asm("fma.rn.f32x2 %0,%1,%2,%3;" : "=l"(d) : "l"(a), "l"(b), "l"(c)); return d;
}
__device__ __forceinline__ u64 fmul2(u64 a, u64 b) {
    u64 d; asm("mul.rn.f32x2 %0,%1,%2;" : "=l"(d) : "l"(a), "l"(b)); return d;
}
__device__ __forceinline__ u64 fadd2(u64 a, u64 b) {
    u64 d; asm("add.rn.f32x2 %0,%1,%2;" : "=l"(d) : "l"(a), "l"(b)); return d;
}

// ---- all weights, pre-packed for f32x2, in constant memory (separate LDC port) ----
struct __align__(16) Wts {
    u64 cw[384];   // conv weights (w,w) pairs, [oc][k][ic]
    u64 w1[256];   // w1 as hidden-output pairs: w1[f][j] = (w1[f,2j], w1[f,2j+1])
    u64 w2[16];    // w2 row pairs (w2[h][0], w2[h][1])
    u64 cb[16];    // conv bias (b,b)
    u64 b1[8];     // b1 output pairs
    u64 b2[2];     // (b2[0], b2[1]) + pad
    u64 g[8];      // ln gamma packed (c, c+8)
    u64 bb[8];     // ln beta  packed (c, c+8)
};
__constant__ Wts cW;
__device__   Wts dStage;

__global__ void prep_kernel(const float* __restrict__ conv_w, const float* __restrict__ conv_b,
                            const float* __restrict__ w1,     const float* __restrict__ b1,
                            const float* __restrict__ w2,     const float* __restrict__ b2,
                            const float* __restrict__ ln_g,   const float* __restrict__ ln_b)
{
    const int tid = threadIdx.x;
    for (int j = tid; j < 384; j += 128) {
        const int oc = j / 24, r = j % 24, ic = r / 3, k = r % 3;   // conv_w is (oc, ic, k)
        const float w = conv_w[j];
        dStage.cw[oc * 24 + k * 8 + ic] = pk(w, w);
    }
    for (int j = tid; j < 256; j += 128) {
        const int f = j / 8, q = j % 8;
        dStage.w1[j] = pk(w1[f * 16 + 2 * q], w1[f * 16 + 2 * q + 1]);
    }
    if (tid < 16) dStage.w2[tid] = pk(w2[2 * tid], w2[2 * tid + 1]);
    if (tid < 16) dStage.cb[tid] = pk(conv_b[tid], conv_b[tid]);
    if (tid < 8)  dStage.b1[tid] = pk(b1[2 * tid], b1[2 * tid + 1]);
    if (tid == 0) { dStage.b2[0] = pk(b2[0], b2[1]); dStage.b2[1] = 0ull; }
    if (tid < 8)  dStage.g[tid]  = pk(ln_g[tid], ln_g[tid + 8]);
    if (tid < 8)  dStage.bb[tid] = pk(ln_b[tid], ln_b[tid + 8]);
}

__global__ __launch_bounds__(THREADS, 4)
void bimanual_kernel(const float* __restrict__ x, float* __restrict__ out)
{
    __shared__ __align__(16) u64 xs[(TILE + 2) * XROW];   // pair-interleaved x tile

    const int tid   = threadIdx.x;
    const int b     = blockIdx.y;
    const int tbase = blockIdx.x * TILE;

    // ---- stage x tile (TILE + 2 halo rows; t<0 rows are the conv zero-padding) ----
    for (int tt = tid; tt < TILE + 2; tt += THREADS) {
        const int t = tbase - 2 + tt;
        u64* row = &xs[tt * XROW];
        if (t >= 0) {
            const float4* p = (const float4*)(x + ((size_t)b * T_ + t) * 16);
            float4 a = p[0], bq = p[1], c = p[2], d = p[3];
            row[0] = pk(a.x,  c.x); row[1] = pk(a.y,  c.y);
            row[2] = pk(a.z,  c.z); row[3] = pk(a.w,  c.w);
            row[4] = pk(bq.x, d.x); row[5] = pk(bq.y, d.y);
            row[6] = pk(bq.z, d.z); row[7] = pk(bq.w, d.w);
        } else {
            #pragma unroll
            for (int j = 0; j < 8; ++j) row[j] = 0ull;
        }
    }
    __syncthreads();

    // ---- per-thread: ITEMS consecutive elements, window rows r0 .. r0+ITEMS+1 ----
    const int r0 = tid * ITEMS;

    // hidden accumulators: 8 packed output-pairs per element
    u64 hid[ITEMS][8];
    #pragma unroll
    for (int j = 0; j < 8; ++j) {
        const u64 bj = cW.b1[j];
        #pragma unroll
        for (int i = 0; i < ITEMS; ++i) hid[i][j] = bj;
    }

    // Scope the x window so it is dead after the conv loop (register pressure).
    {
        u64 xp[ITEMS + 2][8];
        #pragma unroll
        for (int r = 0; r < ITEMS + 2; ++r) {
            const u64* row = &xs[(r0 + r) * XROW];
            #pragma unroll
            for (int ic = 0; ic < 8; ++ic) xp[r][ic] = row[ic];
        }

        // ---- fused conv(+ReLU) -> rank-1 MLP update; weights via constant port ----
        #pragma unroll
        for (int oc = 0; oc < 16; ++oc) {
            u64 acc[ITEMS];
            {
                const u64 cb = cW.cb[oc];
                #pragma unroll
                for (int i = 0; i < ITEMS; ++i) acc[i] = cb;
            }
            #pragma unroll
            for (int k = 0; k < 3; ++k) {
                const ulonglong2* wp = (const ulonglong2*)&cW.cw[oc * 24 + k * 8];
                #pragma unroll
                for (int q = 0; q < 4; ++q) {
                    const ulonglong2 wv = wp[q];      // LDC.128 = 2 packed weight pairs
                    #pragma unroll
                    for (int i = 0; i < ITEMS; ++i)
                        acc[i] = ffma2(xp[i + k][2 * q], wv.x, acc[i]);
                    #pragma unroll
                    for (int i = 0; i < ITEMS; ++i)
                        acc[i] = ffma2(xp[i + k][2 * q + 1], wv.y, acc[i]);
                }
            }
            // ReLU + broadcast-splat per element
            u64 vl[ITEMS], vr[ITEMS];
            #pragma unroll
            for (int i = 0; i < ITEMS; ++i) {
                float hl, hr; upk(acc[i], hl, hr);
                hl = fmaxf(hl, 0.f); hr = fmaxf(hr, 0.f);
                vl[i] = pk(hl, hl); vr[i] = pk(hr, hr);
            }
            // rank-1 update of hidden accs: hid += hl*w1[oc,:] + hr*w1[16+oc,:]
            const ulonglong2* wlr = (const ulonglong2*)&cW.w1[oc * 8];
            const ulonglong2* wrr = (const ulonglong2*)&cW.w1[(16 + oc) * 8];
            #pragma unroll
            for (int q = 0; q < 4; ++q) {
                const ulonglong2 wl = wlr[q];
                const ulonglong2 wr = wrr[q];
                #pragma unroll
                for (int i = 0; i < ITEMS; ++i) {
                    hid[i][2 * q]     = ffma2(vl[i], wl.x, ffma2(vr[i], wr.x, hid[i][2 * q]));
                    hid[i][2 * q + 1] = ffma2(vl[i], wl.y, ffma2(vr[i], wr.y, hid[i][2 * q + 1]));
                }
            }
        }
    } // xp dies here

    // ---- logits + softmax(2): j outer so w2 LDC amortizes over items ----
    u64 lacc[ITEMS];
    {
        const u64 b2v = cW.b2[0];
        #pragma unroll
        for (int i = 0; i < ITEMS; ++i) lacc[i] = b2v;
        const ulonglong2* w2q = (const ulonglong2*)cW.w2;
        #pragma unroll
        for (int j = 0; j < 8; ++j) {
            const ulonglong2 wv = w2q[j];
            #pragma unroll
            for (int i = 0; i < ITEMS; ++i) {
                float h0, h1; upk(hid[i][j], h0, h1);
                h0 = fmaxf(h0, 0.f); h1 = fmaxf(h1, 0.f);
                lacc[i] = ffma2(pk(h0, h0), wv.x, lacc[i]);
                lacc[i] = ffma2(pk(h1, h1), wv.y, lacc[i]);
            }
        }
    }
    float a0v[ITEMS], a1v[ITEMS];
    #pragma unroll
    for (int i = 0; i < ITEMS; ++i) {
        float l0, l1; upk(lacc[i], l0, l1);
        const float e = __expf(l1 - l0);
        a0v[i] = 1.f / (1.f + e);
        a1v[i] = e * a0v[i];
    }

    // ---- gated residual + LayerNorm(16) + stores (x reloaded from smem) ----
    #pragma unroll
    for (int i = 0; i < ITEMS; ++i) {
        const int tglob = tbase + r0 + i;
        const u64* xrow = &xs[(r0 + i + 2) * XROW];
        const u64 sp = pk(1.f + a0v[i], 1.f + a1v[i]);     // y = x * (1 + alpha_side)
        u64 yp[8];
        u64 sum = pk(0.f, 0.f);
        #pragma unroll
        for (int c = 0; c < 8; ++c) { yp[c] = fmul2(xrow[c], sp); sum = fadd2(sum, yp[c]); }
        float sL, sR; upk(sum, sL, sR);
        const float mu   = (sL + sR) * 0.0625f;
        const u64   nmup = pk(-mu, -mu);
        u64 var2 = pk(0.f, 0.f);
        u64 dp[8];
        #pragma unroll
        for (int c = 0; c < 8; ++c) { dp[c] = fadd2(yp[c], nmup); var2 = ffma2(dp[c], dp[c], var2); }
        float vL, vR; upk(var2, vL, vR);
        const float rs  = rsqrtf((vL + vR) * 0.0625f + 1e-5f);
        const u64   rsp = pk(rs, rs);

        float o[16];
        #pragma unroll
        for (int c = 0; c < 8; ++c) {
            const u64 op = ffma2(fmul2(dp[c], rsp), cW.g[c], cW.bb[c]);
            upk(op, o[c], o[c + 8]);
        }

        float4* outX = (float4*)(out + ((size_t)b * T_ + tglob) * 16);
        outX[0] = make_float4(o[0],  o[1],  o[2],  o[3]);
        outX[1] = make_float4(o[4],  o[5],  o[6],  o[7]);
        outX[2] = make_float4(o[8],  o[9],  o[10], o[11]);
        outX[3] = make_float4(o[12], o[13], o[14], o[15]);
        float2* outA = (float2*)(out + (size_t)B_ * T_ * 16 + ((size_t)b * T_ + tglob) * 2);
        *outA = make_float2(a0v[i], a1v[i]);
    }
}

extern "C" void kernel_launch(void* const* d_in, const int* in_sizes, int n_in,
                              void* d_out, int out_size)
{
    const float* x      = (const float*)d_in[0];
    const float* conv_w = (const float*)d_in[1];
    const float* conv_b = (const float*)d_in[2];
    const float* w1     = (const float*)d_in[3];
    const float* b1     = (const float*)d_in[4];
    const float* w2     = (const float*)d_in[5];
    const float* b2     = (const float*)d_in[6];
    const float* ln_g   = (const float*)d_in[7];
    const float* ln_b   = (const float*)d_in[8];

    // 1) pack weights into a device staging struct
    prep_kernel<<<1, 128>>>(conv_w, conv_b, w1, b1, w2, b2, ln_g, ln_b);

    // 2) D2D copy staging -> __constant__ (async, graph-capturable memcpy node)
    void* stage_ptr = nullptr;
    cudaGetSymbolAddress(&stage_ptr, dStage);
    cudaMemcpyToSymbolAsync(cW, stage_ptr, sizeof(Wts), 0, cudaMemcpyDeviceToDevice, 0);

    // 3) main kernel
    dim3 grid(T_ / TILE, B_);
    bimanual_kernel<<<grid, THREADS>>>(x, (float*)d_out);
}